// round 2
// baseline (speedup 1.0000x reference)
#include <cuda_runtime.h>
#include <cstddef>
#include <cstdint>

// CubePadding: x [6,128,512,512] f32, pad=1 -> out [6,128,514,514] f32.
// Faces order: 0=back, 1=down, 2=front, 3=left, 4=right, 5=top.

#define C_   128
#define H_   512
#define W_   512
#define OH_  514
#define OW_  514

__device__ __forceinline__ const float* facePlane(const float* chanBase, int face) {
    // chanBase = in + c*H*W ; plane(face) = in + (face*C + c)*H*W
    return chanBase + (size_t)face * ((size_t)C_ * H_ * W_);
}

// ---- border gathers (p = 1) ----
// h, w are in [0, 511].

__device__ __forceinline__ float load_top(const float* cb, int f, int w) {
    switch (f) {
        case 0: return __ldg(facePlane(cb, 5) + (511 - w));                 // top[0, 511-w]
        case 1: return __ldg(facePlane(cb, 2) + (size_t)511 * W_ + w);      // front[511, w]
        case 2: return __ldg(facePlane(cb, 5) + (size_t)511 * W_ + w);      // top[511, w]
        case 3: return __ldg(facePlane(cb, 5) + (size_t)w * W_);            // top[w, 0]
        case 4: return __ldg(facePlane(cb, 5) + (size_t)(511 - w) * W_ + 511); // top[511-w, 511]
        default:return __ldg(facePlane(cb, 0) + (511 - w));                 // back[0, 511-w]
    }
}

__device__ __forceinline__ float load_bot(const float* cb, int f, int w) {
    switch (f) {
        case 0: return __ldg(facePlane(cb, 1) + (size_t)511 * W_ + (511 - w)); // down[511, 511-w]
        case 1: return __ldg(facePlane(cb, 0) + (size_t)511 * W_ + (511 - w)); // back[511, 511-w]
        case 2: return __ldg(facePlane(cb, 1) + w);                          // down[0, w]
        case 3: return __ldg(facePlane(cb, 1) + (size_t)(511 - w) * W_);     // down[511-w, 0]
        case 4: return __ldg(facePlane(cb, 1) + (size_t)w * W_ + 511);       // down[w, 511]
        default:return __ldg(facePlane(cb, 2) + w);                          // front[0, w]
    }
}

__device__ __forceinline__ float load_left(const float* cb, int f, int h) {
    switch (f) {
        case 0: return __ldg(facePlane(cb, 4) + (size_t)h * W_ + 511);       // right[h, 511]
        case 1: return __ldg(facePlane(cb, 3) + (size_t)511 * W_ + (511 - h)); // left[511, 511-h]
        case 2: return __ldg(facePlane(cb, 3) + (size_t)h * W_ + 511);       // left[h, 511]
        case 3: return __ldg(facePlane(cb, 0) + (size_t)h * W_ + 511);       // back[h, 511]
        case 4: return __ldg(facePlane(cb, 2) + (size_t)h * W_ + 511);       // front[h, 511]
        default:return __ldg(facePlane(cb, 3) + h);                          // left[0, h]
    }
}

__device__ __forceinline__ float load_right(const float* cb, int f, int h) {
    switch (f) {
        case 0: return __ldg(facePlane(cb, 3) + (size_t)h * W_);             // left[h, 0]
        case 1: return __ldg(facePlane(cb, 4) + (size_t)511 * W_ + h);       // right[511, h]
        case 2: return __ldg(facePlane(cb, 4) + (size_t)h * W_);             // right[h, 0]
        case 3: return __ldg(facePlane(cb, 2) + (size_t)h * W_);             // front[h, 0]
        case 4: return __ldg(facePlane(cb, 0) + (size_t)h * W_);             // back[h, 0]
        default:return __ldg(facePlane(cb, 4) + (511 - h));                  // right[0, 511-h]
    }
}

// Grid: (1, 514, 768). blockDim = 256. Each block writes one full output row
// (257 float2, 8B-aligned); thread 0 also handles the last float2 (j=256).
__global__ void __launch_bounds__(256)
cubepad_kernel(const float* __restrict__ in, float* __restrict__ out) {
    const int pz = blockIdx.z;        // f*128 + c
    const int y  = blockIdx.y;        // 0..513
    const int f  = pz >> 7;
    const int c  = pz & 127;
    const int j  = threadIdx.x;       // float2 index within row

    float2* __restrict__ orow =
        reinterpret_cast<float2*>(out + ((size_t)pz * OH_ + y) * OW_);

    const float* __restrict__ plane = in + (size_t)pz * ((size_t)H_ * W_);
    const float* __restrict__ cb    = in + (size_t)c  * ((size_t)H_ * W_);

    if (y >= 1 && y <= H_) {
        // interior row: out[y, x] = in[y-1, x-1] for x in [1,512]; borders at x=0,513
        const float* __restrict__ irow = plane + (size_t)(y - 1) * W_;
        if (j >= 1) {
            // out cols 2j, 2j+1  <-  in cols 2j-1, 2j   (j = 1..255)
            float2 v;
            v.x = __ldg(irow + (2 * j - 1));
            v.y = __ldg(irow + (2 * j));
            orow[j] = v;
        } else {
            const int h = y - 1;
            float2 v0;                      // out cols 0 (left border), 1 (in col 0)
            v0.x = load_left(cb, f, h);
            v0.y = __ldg(irow);
            orow[0] = v0;
            float2 v1;                      // out cols 512 (in col 511), 513 (right border)
            v1.x = __ldg(irow + 511);
            v1.y = load_right(cb, f, h);
            orow[256] = v1;
        }
    } else {
        // top (y==0) or bottom (y==513) row; corners replicate strip endpoints
        const bool top = (y == 0);
        #pragma unroll
        for (int pass = 0; pass < 2; ++pass) {
            int jj = (pass == 0) ? j : 256;
            if (pass == 1 && j != 0) break;
            int x0 = 2 * jj, x1 = 2 * jj + 1;
            int w0 = x0 - 1; w0 = w0 < 0 ? 0 : (w0 > 511 ? 511 : w0);
            int w1 = x1 - 1; w1 = w1 > 511 ? 511 : w1;   // x1 >= 1 always
            float2 v;
            if (top) { v.x = load_top(cb, f, w0); v.y = load_top(cb, f, w1); }
            else     { v.x = load_bot(cb, f, w0); v.y = load_bot(cb, f, w1); }
            orow[jj] = v;
        }
    }
}

extern "C" void kernel_launch(void* const* d_in, const int* in_sizes, int n_in,
                              void* d_out, int out_size) {
    const float* x = (const float*)d_in[0];
    float* out = (float*)d_out;
    (void)in_sizes; (void)n_in; (void)out_size;  // shapes fixed by problem; pad = 1

    dim3 grid(1, OH_, 6 * C_);
    dim3 block(256);
    cubepad_kernel<<<grid, block>>>(x, out);
}